// round 7
// baseline (speedup 1.0000x reference)
#include <cuda_runtime.h>
#include <math.h>
#include <stdint.h>

// Problem constants: B=1, C=256, H=W=96
#define C_DIM 256
#define HDIM  96
#define HW    9216          // H*W
#define CW    24576         // C*W
#define NPIX  (C_DIM*HW)    // 2359296

// Scratch (device globals; no allocation allowed)
__device__ float g_FQ[NPIX];     // frequency-filtered map (input to Q conv)
__device__ float g_FQM[CW];      // Fuse_Q_mask: max over strided rows of Q
__device__ float g_SF[C_DIM*32]; // per-channel 16 complex DFT coefficients
__device__ float g_TWC[96], g_TWS[96];

// ---------------------------------------------------------------------------
__device__ __forceinline__ void cp_async16(uint32_t dst, const void* src) {
    asm volatile("cp.async.cg.shared.global [%0], [%1], 16;\n" :: "r"(dst), "l"(src));
}
#define CP_ASYNC_COMMIT() asm volatile("cp.async.commit_group;\n")
#define CP_ASYNC_WAIT0()  asm volatile("cp.async.wait_group 0;\n")

__device__ __forceinline__ void atomicMaxFloat(float* addr, float val) {
    if (val >= 0.0f) atomicMax((int*)addr, __float_as_int(val));
    else             atomicMin((unsigned int*)addr, __float_as_uint(val));
}

// ---------------------------------------------------------------------------
// ANALYSIS: per-channel |x| -> min/max -> q=floor(255*(a-mn)/ptp) -> 16
// complex DFT coefficients for the fftshift-centered 4x4 freq box (kr,kc in
// {-2..1}). Writes g_SF[ch*32 .. +31]. One block per channel, 256 threads.
// Blocks ch<96 also init g_FQM; block 0 publishes the twiddle table.
__global__ __launch_bounds__(256) void freq_analysis(const float* __restrict__ x) {
    __shared__ float sa[HW];                  // 36864 B
    __shared__ float twc[96], tws[96];
    __shared__ unsigned char pidx[4][96];     // ((k-2)*v) mod 96
    __shared__ float Gp[2][4][96][2];         // stage1 partials (half,kr,w,re/im)
    __shared__ float s2p[64][2];              // stage2 quarter partials
    __shared__ float sMin[8], sMax[8];

    const int ch  = blockIdx.x;
    const int tid = threadIdx.x;
    const float* xc = x + ch * HW;

    if (ch < 96) g_FQM[ch * 256 + tid] = -INFINITY;   // init Fuse_Q_mask buffer

    if (tid < 96) {  // twiddles, fp64 trig
        double th = 2.0 * 3.14159265358979323846 * (double)tid / 96.0;
        twc[tid] = (float)cos(th);
        tws[tid] = (float)sin(th);
        if (ch == 0) { g_TWC[tid] = twc[tid]; g_TWS[tid] = tws[tid]; }
    }
    for (int t = tid; t < 384; t += 256) {    // phase index table
        int k = t / 96, v = t - k * 96;
        int m = ((k - 2) * v) % 96; if (m < 0) m += 96;
        pidx[k][v] = (unsigned char)m;
    }

    float lmin = INFINITY, lmax = -INFINITY;
    for (int i = tid; i < HW; i += 256) {
        float a = fabsf(xc[i]);
        sa[i] = a;
        lmin = fminf(lmin, a);
        lmax = fmaxf(lmax, a);
    }
    #pragma unroll
    for (int off = 16; off; off >>= 1) {
        lmin = fminf(lmin, __shfl_down_sync(0xffffffffu, lmin, off));
        lmax = fmaxf(lmax, __shfl_down_sync(0xffffffffu, lmax, off));
    }
    const int wid = tid >> 5, lane = tid & 31;
    if (lane == 0) { sMin[wid] = lmin; sMax[wid] = lmax; }
    __syncthreads();

    float mn = sMin[0], mx = sMax[0];
    #pragma unroll
    for (int j = 1; j < 8; j++) { mn = fminf(mn, sMin[j]); mx = fmaxf(mx, sMax[j]); }
    const float ptp = mx - mn;

    // ---- stage 1: column DFT over h (4 row-freqs), q computed on the fly --
    if (tid < 192) {
        const int w  = tid >> 1;
        const int h0 = (tid & 1) * 48;
        float gr[4] = {0.f, 0.f, 0.f, 0.f};
        float gi[4] = {0.f, 0.f, 0.f, 0.f};
        for (int j = 0; j < 48; j++) {
            int h = h0 + j;
            float q = floorf(__fdiv_rn(255.0f * (sa[h * 96 + w] - mn), ptp));
            #pragma unroll
            for (int kr = 0; kr < 4; kr++) {
                int m = pidx[kr][h];
                gr[kr] += q * twc[m];   // e^{-i th}: (cos, -sin)
                gi[kr] -= q * tws[m];
            }
        }
        #pragma unroll
        for (int kr = 0; kr < 4; kr++) {
            Gp[tid & 1][kr][w][0] = gr[kr];
            Gp[tid & 1][kr][w][1] = gi[kr];
        }
    }
    __syncthreads();

    // ---- stage 2: 16 coefficients, 64-way parallel then 4:1 combine -------
    if (tid < 64) {
        int coef = tid >> 2, q4 = tid & 3;
        int kr = coef >> 2, kc = coef & 3;
        float fr = 0.f, fi = 0.f;
        int w0 = q4 * 24;
        for (int w = w0; w < w0 + 24; w++) {
            float grw = Gp[0][kr][w][0] + Gp[1][kr][w][0];
            float giw = Gp[0][kr][w][1] + Gp[1][kr][w][1];
            int m = pidx[kc][w];
            float cc = twc[m], ss = tws[m];
            fr += grw * cc + giw * ss;      // (grw + i giw) * (cos - i sin)
            fi += giw * cc - grw * ss;
        }
        s2p[tid][0] = fr;
        s2p[tid][1] = fi;
    }
    __syncthreads();
    if (tid < 32) {
        int coef = tid >> 1, ri = tid & 1;
        float s = s2p[coef * 4][ri] + s2p[coef * 4 + 1][ri]
                + s2p[coef * 4 + 2][ri] + s2p[coef * 4 + 3][ri];
        g_SF[ch * 32 + coef * 2 + ri] = s;
    }
}

// ---------------------------------------------------------------------------
// SYNTHESIS: g_FQ[ch,h,w] = |sum_{kr,kc} F e^{+i...}| / 9216 from 16 coefs.
// One block per channel, 256 threads, fully parallel per-pixel work.
__global__ __launch_bounds__(256) void freq_synth() {
    __shared__ float twc[96], tws[96];
    __shared__ unsigned char pidx[4][96];
    __shared__ float sF[32];
    __shared__ float sP[4][96][2];   // column partials over kc

    const int ch  = blockIdx.x;
    const int tid = threadIdx.x;

    if (tid < 96) { twc[tid] = g_TWC[tid]; tws[tid] = g_TWS[tid]; }
    if (tid >= 96 && tid < 128) sF[tid - 96] = g_SF[ch * 32 + (tid - 96)];
    for (int t = tid; t < 384; t += 256) {
        int k = t / 96, v = t - k * 96;
        int m = ((k - 2) * v) % 96; if (m < 0) m += 96;
        pidx[k][v] = (unsigned char)m;
    }
    __syncthreads();

    if (tid < 96) {
        int w = tid;
        #pragma unroll
        for (int kr = 0; kr < 4; kr++) {
            float pre = 0.f, pim = 0.f;
            #pragma unroll
            for (int kc = 0; kc < 4; kc++) {
                int m = pidx[kc][w];
                float fr = sF[2 * (kr * 4 + kc)], fi = sF[2 * (kr * 4 + kc) + 1];
                float cc = twc[m], ss = tws[m];     // e^{+i th}
                pre += fr * cc - fi * ss;
                pim += fr * ss + fi * cc;
            }
            sP[kr][w][0] = pre;
            sP[kr][w][1] = pim;
        }
    }
    __syncthreads();

    const float inv = 1.0f / 9216.0f;
    for (int i = tid; i < HW; i += 256) {
        int h = i / 96, w = i - h * 96;     // const-div -> mul.hi
        float re = 0.f, im = 0.f;
        #pragma unroll
        for (int kr = 0; kr < 4; kr++) {
            int m = pidx[kr][h];
            float cc = twc[m], ss = tws[m];
            float pre = sP[kr][w][0], pim = sP[kr][w][1];
            re += pre * cc - pim * ss;
            im += pre * ss + pim * cc;
        }
        g_FQ[ch * HW + i] = sqrtf(re * re + im * im) * inv;
    }
}

// ---------------------------------------------------------------------------
// SGEMM  acc[o,p] = sum_c W[o,c]*X[c,p] + bias[o],  O=256, P=9216, K=256.
// 128x64 tile, BK=16, 256 threads (8x4/thread), 2 CTAs/SM, cp.async double
// buffer for B, register-staged transposed A, register double-buffer on kk.
// MODE 0 (Q): X = g_FQ, epilogue tree-max pre-reduction into g_FQM
// MODE 2 (V): X = fuse, epilogue writes raw (acc+bias) to out
template <int MODE>
__global__ __launch_bounds__(256, 2) void gemm_kernel(
    const float* __restrict__ Wm,
    const float* __restrict__ Xin,
    const float* __restrict__ bias,
    float* __restrict__ out)
{
    const float* X = (MODE == 0) ? (const float*)g_FQ : Xin;
    // Unified smem: As = [2][16][132] (4224 floats), Bs = [2][16][64] (2048)
    __shared__ float smem_all[4224 + 2048];
    float* AsBase = smem_all;
    float* BsBase = smem_all + 4224;

    const int tid = threadIdx.x;
    const int p0 = blockIdx.x * 64;
    const int o0 = blockIdx.y * 128;
    const int tm = tid >> 4, tn = tid & 15;

    const int arow = tid >> 2, acol = (tid & 3) * 4;
    const int brow = tid >> 4, bcol = (tid & 15) * 4;

    const float* Aptr = Wm + (o0 + arow) * 256 + acol;
    const float* Bptr = X + brow * HW + p0 + bcol;

    // ---- prologue: tile k0=0 --------------------------------------------
    float4 a0 = *(const float4*)(Aptr);
    float4 a1 = *(const float4*)(Aptr + 64 * 256);
    {
        uint32_t sB = (uint32_t)__cvta_generic_to_shared(BsBase + brow * 64 + bcol);
        cp_async16(sB, Bptr);
        CP_ASYNC_COMMIT();
    }
    {
        float* A0 = AsBase;
        A0[(acol + 0) * 132 + arow] = a0.x; A0[(acol + 1) * 132 + arow] = a0.y;
        A0[(acol + 2) * 132 + arow] = a0.z; A0[(acol + 3) * 132 + arow] = a0.w;
        A0[(acol + 0) * 132 + arow + 64] = a1.x; A0[(acol + 1) * 132 + arow + 64] = a1.y;
        A0[(acol + 2) * 132 + arow + 64] = a1.z; A0[(acol + 3) * 132 + arow + 64] = a1.w;
    }
    CP_ASYNC_WAIT0();
    __syncthreads();

    float accv[8][4];
    #pragma unroll
    for (int i = 0; i < 8; i++)
        #pragma unroll
        for (int j = 0; j < 4; j++) accv[i][j] = 0.f;

    #pragma unroll 1
    for (int k0i = 0; k0i < 16; k0i++) {
        const int buf = k0i & 1;
        const float* Ab = AsBase + buf * 2112;     // 16*132
        const float* Bb = BsBase + buf * 1024;     // 16*64

        if (k0i < 15) {   // prefetch next tile
            const float* An = Aptr + (k0i + 1) * 16;
            a0 = *(const float4*)(An);
            a1 = *(const float4*)(An + 64 * 256);
            uint32_t sBn = (uint32_t)__cvta_generic_to_shared(
                BsBase + (buf ^ 1) * 1024 + brow * 64 + bcol);
            cp_async16(sBn, Bptr + (size_t)(k0i + 1) * 16 * HW);
            CP_ASYNC_COMMIT();
        }

        float ar[2][8], br[2][4];
        *(float4*)(ar[0])     = *(const float4*)(Ab + tm * 8);
        *(float4*)(ar[0] + 4) = *(const float4*)(Ab + tm * 8 + 4);
        *(float4*)(br[0])     = *(const float4*)(Bb + tn * 4);

        #pragma unroll
        for (int kk = 0; kk < 16; kk++) {
            const int cur = kk & 1, nx = cur ^ 1;
            if (kk < 15) {
                *(float4*)(ar[nx])     = *(const float4*)(Ab + (kk + 1) * 132 + tm * 8);
                *(float4*)(ar[nx] + 4) = *(const float4*)(Ab + (kk + 1) * 132 + tm * 8 + 4);
                *(float4*)(br[nx])     = *(const float4*)(Bb + (kk + 1) * 64 + tn * 4);
            }
            #pragma unroll
            for (int i = 0; i < 8; i++)
                #pragma unroll
                for (int j = 0; j < 4; j++)
                    accv[i][j] += ar[cur][i] * br[cur][j];
        }

        if (k0i < 15) {
            float* An_ = AsBase + (buf ^ 1) * 2112;
            An_[(acol + 0) * 132 + arow] = a0.x; An_[(acol + 1) * 132 + arow] = a0.y;
            An_[(acol + 2) * 132 + arow] = a0.z; An_[(acol + 3) * 132 + arow] = a0.w;
            An_[(acol + 0) * 132 + arow + 64] = a1.x; An_[(acol + 1) * 132 + arow + 64] = a1.y;
            An_[(acol + 2) * 132 + arow + 64] = a1.z; An_[(acol + 3) * 132 + arow + 64] = a1.w;
            CP_ASYNC_WAIT0();
        }
        __syncthreads();
    }

    // ---- epilogue --------------------------------------------------------
    if (MODE == 0) {
        // o0 % 8 == 0 -> row class (o & 7) == i. Two half-passes over i.
        // Stage layout [cls4*64 + pcol][tm] with *17 pad; reduce over tm.
        float* stage = smem_all;   // 4352 floats needed <= 6272 available
        #pragma unroll
        for (int half = 0; half < 2; half++) {
            __syncthreads();
            #pragma unroll
            for (int i2 = 0; i2 < 4; i2++) {
                int i = half * 4 + i2;
                float bo = bias[o0 + tm * 8 + i];
                #pragma unroll
                for (int j = 0; j < 4; j++)
                    stage[(i2 * 64 + tn * 4 + j) * 17 + tm] = accv[i][j] + bo;
            }
            __syncthreads();
            {
                int t = tid;   // 256 cols (4 classes x 64 pcols), one each
                float m = stage[t * 17];
                #pragma unroll
                for (int r = 1; r < 16; r++) m = fmaxf(m, stage[t * 17 + r]);
                int cls = half * 4 + (t >> 6), pcol = t & 63;
                unsigned idx = ((unsigned)cls * 9216u + (unsigned)(p0 + pcol)) % 24576u;
                atomicMaxFloat(&g_FQM[idx], m);
            }
        }
    } else {
        #pragma unroll
        for (int i = 0; i < 8; i++) {
            int o = o0 + tm * 8 + i;
            float bo = bias[o];
            float4 v;
            v.x = accv[i][0] + bo;
            v.y = accv[i][1] + bo;
            v.z = accv[i][2] + bo;
            v.w = accv[i][3] + bo;
            *(float4*)(out + (size_t)o * HW + p0 + tn * 4) = v;
        }
    }
}

// ---------------------------------------------------------------------------
// out[e] *= (1 + g_FQM[e % 24576]), vectorized float4 (24576 % 4 == 0).
__global__ __launch_bounds__(256) void mask_epilogue(float* __restrict__ out) {
    unsigned v = blockIdx.x * 256u + threadIdx.x;    // float4 index
    unsigned e = v * 4u;
    unsigned idx = e % 24576u;
    float4 o = ((float4*)out)[v];
    float4 m = *(const float4*)&g_FQM[idx];
    o.x *= (1.0f + m.x);
    o.y *= (1.0f + m.y);
    o.z *= (1.0f + m.z);
    o.w *= (1.0f + m.w);
    ((float4*)out)[v] = o;
}

// ---------------------------------------------------------------------------
extern "C" void kernel_launch(void* const* d_in, const int* in_sizes, int n_in,
                              void* d_out, int out_size) {
    const float* fuse = (const float*)d_in[0];
    const float* Wq   = (const float*)d_in[1];
    const float* bq   = (const float*)d_in[2];
    // d_in[3] (Wk), d_in[4] (bk): dead code — softmax over batch axis of size 1
    const float* Wv   = (const float*)d_in[5];
    const float* bv   = (const float*)d_in[6];
    float* out = (float*)d_out;

    static cudaStream_t s1 = nullptr;
    static cudaEvent_t evRoot = nullptr, evSide = nullptr;
    if (s1 == nullptr) {
        cudaStreamCreateWithFlags(&s1, cudaStreamNonBlocking);
        cudaEventCreateWithFlags(&evRoot, cudaEventDisableTiming);
        cudaEventCreateWithFlags(&evSide, cudaEventDisableTiming);
    }

    // Fork: V-GEMM mainloop is independent of the freq/Q path.
    cudaEventRecord(evRoot, 0);
    cudaStreamWaitEvent(s1, evRoot, 0);
    gemm_kernel<2><<<dim3(144, 2), 256, 0, s1>>>(Wv, fuse, bv, out);
    cudaEventRecord(evSide, s1);

    // Main stream: freq analysis -> synthesis -> Q-GEMM (produces g_FQM).
    freq_analysis<<<C_DIM, 256>>>(fuse);     // also inits g_FQM
    freq_synth<<<C_DIM, 256>>>();
    gemm_kernel<0><<<dim3(144, 2), 256>>>(Wq, nullptr, bq, nullptr);

    // Join, then apply mask in-place on out.
    cudaStreamWaitEvent(0, evSide, 0);
    mask_epilogue<<<NPIX / 4 / 256, 256>>>(out);
}

// round 10
// speedup vs baseline: 1.2722x; 1.2722x over previous
#include <cuda_runtime.h>
#include <cuda_bf16.h>
#include <math.h>
#include <stdint.h>

// Problem constants: B=1, C=256, H=W=96
#define C_DIM 256
#define HDIM  96
#define HW    9216          // H*W
#define CW    24576         // C*W
#define NPIX  (C_DIM*HW)    // 2359296

// ---------------------------------------------------------------------------
// Device-global scratch. bf16 split-precision copies, packed bf16x2 (uint32).
__device__ uint32_t g_Xh[NPIX/2],  g_Xl[NPIX/2];    // fuse  hi/lo  [c][p/2]
__device__ uint32_t g_FQh[NPIX/2], g_FQl[NPIX/2];   // FQ    hi/lo  [c][p/2]
__device__ uint32_t g_Wh0[32768], g_Wl0[32768];     // Wq    hi/lo  [o][c/2]
__device__ uint32_t g_Wh1[32768], g_Wl1[32768];     // Wv    hi/lo  [o][c/2]
__device__ float    g_FQM[CW];                      // Fuse_Q_mask

// ---------------------------------------------------------------------------
__device__ __forceinline__ void atomicMaxFloat(float* addr, float val) {
    if (val >= 0.0f) atomicMax((int*)addr, __float_as_int(val));
    else             atomicMin((unsigned int*)addr, __float_as_uint(val));
}

__device__ __forceinline__ uint32_t pack_bf2(float a, float b) {
    __nv_bfloat16 ha = __float2bfloat16_rn(a);
    __nv_bfloat16 hb = __float2bfloat16_rn(b);
    unsigned short ua = *reinterpret_cast<unsigned short*>(&ha);
    unsigned short ub = *reinterpret_cast<unsigned short*>(&hb);
    return (uint32_t)ua | ((uint32_t)ub << 16);
}
__device__ __forceinline__ float bf_hi_val(float a) {
    __nv_bfloat16 h = __float2bfloat16_rn(a);
    return __bfloat162float(h);
}

// m16n8k16 bf16 MMA, fp32 accumulate (standard PTX, compiles on plain sm_103)
__device__ __forceinline__ void mma16816(float* d, const uint32_t* a,
                                         const uint32_t* b) {
    asm volatile(
        "mma.sync.aligned.m16n8k16.row.col.f32.bf16.bf16.f32 "
        "{%0,%1,%2,%3}, {%4,%5,%6,%7}, {%8,%9}, {%0,%1,%2,%3};"
        : "+f"(d[0]), "+f"(d[1]), "+f"(d[2]), "+f"(d[3])
        : "r"(a[0]), "r"(a[1]), "r"(a[2]), "r"(a[3]), "r"(b[0]), "r"(b[1]));
}

// ---------------------------------------------------------------------------
// Convert fuse, Wq, Wv to split bf16 hi/lo pairs. float4 per thread.
__global__ __launch_bounds__(256) void convert_kernel(
    const float* __restrict__ fuse, const float* __restrict__ Wq,
    const float* __restrict__ Wv)
{
    unsigned v = blockIdx.x * 256u + threadIdx.x;   // float4 index
    const float* src; uint32_t *dh, *dl; unsigned base;
    if (v < NPIX/4)                 { src = fuse; dh = g_Xh;  dl = g_Xl;  base = v; }
    else if (v < NPIX/4 + 16384)    { src = Wq;   dh = g_Wh0; dl = g_Wl0; base = v - NPIX/4; }
    else if (v < NPIX/4 + 32768)    { src = Wv;   dh = g_Wh1; dl = g_Wl1; base = v - NPIX/4 - 16384; }
    else return;
    float4 x = ((const float4*)src)[base];
    float h0 = bf_hi_val(x.x), h1 = bf_hi_val(x.y);
    float h2 = bf_hi_val(x.z), h3 = bf_hi_val(x.w);
    dh[2*base]   = pack_bf2(x.x, x.y);
    dh[2*base+1] = pack_bf2(x.z, x.w);
    dl[2*base]   = pack_bf2(x.x - h0, x.y - h1);
    dl[2*base+1] = pack_bf2(x.z - h2, x.w - h3);
}

// ---------------------------------------------------------------------------
// Per-channel frequency filter (proven R6 kernel), emitting bf16 hi/lo FQ.
// Keep DFT freqs kr,kc in {-2..1} (fftshift-centered 4x4 box), inverse-
// synthesize, abs, /9216. One block per channel, 256 threads.
__global__ __launch_bounds__(256) void freq_kernel(const float* __restrict__ x) {
    __shared__ float sa[HW];                  // 36864 B
    __shared__ float twc[96], tws[96];
    __shared__ unsigned char pidx[4][96];     // ((k-2)*v) mod 96
    __shared__ float Gp[2][4][96][2];         // stage1 partials
    __shared__ float s2p[64][2];              // stage2 quarter partials
    __shared__ float sF[32];                  // 16 complex coefficients
    __shared__ float sP[4][96][2];            // synthesis column partials
    __shared__ float sMin[8], sMax[8];

    const int ch  = blockIdx.x;
    const int tid = threadIdx.x;
    const float* xc = x + ch * HW;

    if (ch < 96) g_FQM[ch * 256 + tid] = -INFINITY;   // init Fuse_Q_mask buffer

    if (tid < 96) {  // twiddles, fp64 trig
        double th = 2.0 * 3.14159265358979323846 * (double)tid / 96.0;
        twc[tid] = (float)cos(th);
        tws[tid] = (float)sin(th);
    }
    for (int t = tid; t < 384; t += 256) {    // phase index table
        int k = t / 96, v = t - k * 96;
        int m = ((k - 2) * v) % 96; if (m < 0) m += 96;
        pidx[k][v] = (unsigned char)m;
    }

    float lmin = INFINITY, lmax = -INFINITY;
    for (int i = tid; i < HW; i += 256) {
        float a = fabsf(xc[i]);
        sa[i] = a;
        lmin = fminf(lmin, a);
        lmax = fmaxf(lmax, a);
    }
    #pragma unroll
    for (int off = 16; off; off >>= 1) {
        lmin = fminf(lmin, __shfl_down_sync(0xffffffffu, lmin, off));
        lmax = fmaxf(lmax, __shfl_down_sync(0xffffffffu, lmax, off));
    }
    const int wid = tid >> 5, lane = tid & 31;
    if (lane == 0) { sMin[wid] = lmin; sMax[wid] = lmax; }
    __syncthreads();

    float mn = sMin[0], mx = sMax[0];
    #pragma unroll
    for (int j = 1; j < 8; j++) { mn = fminf(mn, sMin[j]); mx = fmaxf(mx, sMax[j]); }
    const float ptp = mx - mn;

    // ---- stage 1: column DFT over h (4 row-freqs) -------------------------
    if (tid < 192) {
        const int w  = tid >> 1;
        const int h0 = (tid & 1) * 48;
        float gr[4] = {0.f, 0.f, 0.f, 0.f};
        float gi[4] = {0.f, 0.f, 0.f, 0.f};
        for (int j = 0; j < 48; j++) {
            int h = h0 + j;
            float q = floorf(__fdiv_rn(255.0f * (sa[h * 96 + w] - mn), ptp));
            #pragma unroll
            for (int kr = 0; kr < 4; kr++) {
                int m = pidx[kr][h];
                gr[kr] += q * twc[m];
                gi[kr] -= q * tws[m];
            }
        }
        #pragma unroll
        for (int kr = 0; kr < 4; kr++) {
            Gp[tid & 1][kr][w][0] = gr[kr];
            Gp[tid & 1][kr][w][1] = gi[kr];
        }
    }
    __syncthreads();

    // ---- stage 2: 16 coefficients, 64-way parallel then 4:1 combine -------
    if (tid < 64) {
        int coef = tid >> 2, q4 = tid & 3;
        int kr = coef >> 2, kc = coef & 3;
        float fr = 0.f, fi = 0.f;
        int w0 = q4 * 24;
        for (int w = w0; w < w0 + 24; w++) {
            float grw = Gp[0][kr][w][0] + Gp[1][kr][w][0];
            float giw = Gp[0][kr][w][1] + Gp[1][kr][w][1];
            int m = pidx[kc][w];
            float cc = twc[m], ss = tws[m];
            fr += grw * cc + giw * ss;
            fi += giw * cc - grw * ss;
        }
        s2p[tid][0] = fr;
        s2p[tid][1] = fi;
    }
    __syncthreads();
    if (tid < 32) {
        int coef = tid >> 1, ri = tid & 1;
        sF[coef * 2 + ri] = s2p[coef * 4][ri] + s2p[coef * 4 + 1][ri]
                          + s2p[coef * 4 + 2][ri] + s2p[coef * 4 + 3][ri];
    }
    __syncthreads();

    // ---- synthesis: column partials over kc ------------------------------
    if (tid < 96) {
        int w = tid;
        #pragma unroll
        for (int kr = 0; kr < 4; kr++) {
            float pre = 0.f, pim = 0.f;
            #pragma unroll
            for (int kc = 0; kc < 4; kc++) {
                int m = pidx[kc][w];
                float fr = sF[2 * (kr * 4 + kc)], fi = sF[2 * (kr * 4 + kc) + 1];
                float cc = twc[m], ss = tws[m];
                pre += fr * cc - fi * ss;
                pim += fr * ss + fi * cc;
            }
            sP[kr][w][0] = pre;
            sP[kr][w][1] = pim;
        }
    }
    __syncthreads();

    // ---- per-pixel-pair inverse + abs, emitted as bf16 hi/lo --------------
    const float inv = 1.0f / 9216.0f;
    for (int i2 = tid; i2 < HW/2; i2 += 256) {
        int h = i2 / 48, w0 = (i2 - h * 48) * 2;
        float v[2];
        #pragma unroll
        for (int dw = 0; dw < 2; dw++) {
            float re = 0.f, im = 0.f;
            #pragma unroll
            for (int kr = 0; kr < 4; kr++) {
                int m = pidx[kr][h];
                float cc = twc[m], ss = tws[m];
                float pre = sP[kr][w0 + dw][0], pim = sP[kr][w0 + dw][1];
                re += pre * cc - pim * ss;
                im += pre * ss + pim * cc;
            }
            v[dw] = sqrtf(re * re + im * im) * inv;
        }
        float h0 = bf_hi_val(v[0]), h1 = bf_hi_val(v[1]);
        g_FQh[ch * (HW/2) + i2] = pack_bf2(v[0], v[1]);
        g_FQl[ch * (HW/2) + i2] = pack_bf2(v[0] - h0, v[1] - h1);
    }
}

// ---------------------------------------------------------------------------
// Split-precision bf16 GEMM via mma.sync.m16n8k16 (HMMA tensor pipe).
// out[o,p] = sum_c W[o,c] X[c,p] + bias[o],  O=256, P=9216, K=256.
// CTA tile: M=128 x N=128, K in two staged phases of 128. 8 warps as 2m x 4n
// (warp tile 64x32). 3 MMA passes: Ah*Bh + Ah*Bl + Al*Bh, fp32 accum.
// MODE 0 (Q): X = FQ, epilogue class-max into g_FQM.
// MODE 1 (V): X = fuse, writes raw (acc+bias) to out.
#define APITCH 68            // u32 words per smem row (136 bf16, conflict-free)
#define AH_OFF 0
#define AL_OFF 8704          // 128*68
#define BH_OFF 17408
#define BL_OFF 26112
#define SMEM_U32 34816       // total u32 words (139264 bytes)

template <int MODE>
__global__ __launch_bounds__(256) void gemm_mma(
    const float* __restrict__ bias, float* __restrict__ out)
{
    extern __shared__ uint32_t su[];
    const int tid  = threadIdx.x;
    const int wid  = tid >> 5, lane = tid & 31;
    const int mw   = wid >> 2, nw = wid & 3;     // 2m x 4n warp grid
    const int gq   = lane >> 2, l4 = lane & 3;   // groupID, threadID-in-group
    const int p0   = blockIdx.x * 128;
    const int o0   = blockIdx.y * 128;

    const uint32_t* Ah = (MODE == 0) ? g_Wh0 : g_Wh1;
    const uint32_t* Al = (MODE == 0) ? g_Wl0 : g_Wl1;
    const uint32_t* Xh = (MODE == 0) ? g_FQh : g_Xh;
    const uint32_t* Xl = (MODE == 0) ? g_FQl : g_Xl;

    float acc[4][4][4];
    #pragma unroll
    for (int mi = 0; mi < 4; mi++)
        #pragma unroll
        for (int ni = 0; ni < 4; ni++)
            #pragma unroll
            for (int r = 0; r < 4; r++) acc[mi][ni][r] = 0.f;

    #pragma unroll 1
    for (int kb = 0; kb < 2; kb++) {
        // ---- stage A tile: 128 o-rows x 128 c (this K phase), hi+lo -------
        #pragma unroll 4
        for (int f = tid; f < 2048; f += 256) {
            int o = f >> 4, q = f & 15;           // 16 uint4 (=128 c) per row
            uint4 vh = ((const uint4*)Ah)[(o0 + o) * 32 + kb * 16 + q];
            uint4 vl = ((const uint4*)Al)[(o0 + o) * 32 + kb * 16 + q];
            ((uint4*)(su + AH_OFF))[o * 17 + q] = vh;   // 68 u32 = 17 uint4/row
            ((uint4*)(su + AL_OFF))[o * 17 + q] = vl;
        }
        // ---- stage B tile transposed: Bs[p=128][c=128], hi+lo -------------
        #pragma unroll 4
        for (int f = tid; f < 8192; f += 256) {
            int c = f >> 6, j = f & 63;           // j = p-pair index
            uint32_t vh = Xh[(size_t)(kb * 128 + c) * 4608 + (p0 >> 1) + j];
            uint32_t vl = Xl[(size_t)(kb * 128 + c) * 4608 + (p0 >> 1) + j];
            unsigned short* Bh16 = (unsigned short*)(su + BH_OFF);
            unsigned short* Bl16 = (unsigned short*)(su + BL_OFF);
            Bh16[(2*j)     * 136 + c] = (unsigned short)(vh & 0xffffu);
            Bh16[(2*j + 1) * 136 + c] = (unsigned short)(vh >> 16);
            Bl16[(2*j)     * 136 + c] = (unsigned short)(vl & 0xffffu);
            Bl16[(2*j + 1) * 136 + c] = (unsigned short)(vl >> 16);
        }
        __syncthreads();

        // ---- compute: 8 k-steps of 16 -------------------------------------
        #pragma unroll 1
        for (int ks = 0; ks < 8; ks++) {
            const int k0w = ks * 8;               // u32 offset within row
            uint32_t bh[4][2], bl[4][2];
            #pragma unroll
            for (int ni = 0; ni < 4; ni++) {
                int n = nw * 32 + ni * 8 + gq;
                int base = n * APITCH + k0w + l4;
                bh[ni][0] = su[BH_OFF + base];
                bh[ni][1] = su[BH_OFF + base + 4];
                bl[ni][0] = su[BL_OFF + base];
                bl[ni][1] = su[BL_OFF + base + 4];
            }
            #pragma unroll
            for (int mi = 0; mi < 4; mi++) {
                int row = mw * 64 + mi * 16 + gq;
                int base = row * APITCH + k0w + l4;
                uint32_t ah[4], al[4];
                ah[0] = su[AH_OFF + base];
                ah[1] = su[AH_OFF + base + 8 * APITCH];
                ah[2] = su[AH_OFF + base + 4];
                ah[3] = su[AH_OFF + base + 8 * APITCH + 4];
                al[0] = su[AL_OFF + base];
                al[1] = su[AL_OFF + base + 8 * APITCH];
                al[2] = su[AL_OFF + base + 4];
                al[3] = su[AL_OFF + base + 8 * APITCH + 4];
                #pragma unroll
                for (int ni = 0; ni < 4; ni++) {
                    mma16816(acc[mi][ni], ah, bh[ni]);
                    mma16816(acc[mi][ni], ah, bl[ni]);
                    mma16816(acc[mi][ni], al, bh[ni]);
                }
            }
        }
        __syncthreads();
    }

    // ---- epilogue --------------------------------------------------------
    if (MODE == 1) {
        #pragma unroll
        for (int mi = 0; mi < 4; mi++) {
            int o = o0 + mw * 64 + mi * 16 + gq;
            float b0 = bias[o], b1 = bias[o + 8];
            #pragma unroll
            for (int ni = 0; ni < 4; ni++) {
                int p = p0 + nw * 32 + ni * 8 + l4 * 2;
                float2 v0 = { acc[mi][ni][0] + b0, acc[mi][ni][1] + b0 };
                float2 v1 = { acc[mi][ni][2] + b1, acc[mi][ni][3] + b1 };
                *(float2*)(out + (size_t)o * HW + p)       = v0;
                *(float2*)(out + (size_t)(o + 8) * HW + p) = v1;
            }
        }
    } else {
        // class = o mod 8 == gq for every value this thread holds
        float* red = (float*)su;                 // 8 x 128
        for (int t = tid; t < 1024; t += 256) red[t] = -INFINITY;
        __syncthreads();
        float bo[4][2];
        #pragma unroll
        for (int mi = 0; mi < 4; mi++) {
            int o = o0 + mw * 64 + mi * 16 + gq;
            bo[mi][0] = bias[o];
            bo[mi][1] = bias[o + 8];
        }
        #pragma unroll
        for (int ni = 0; ni < 4; ni++) {
            #pragma unroll
            for (int l = 0; l < 2; l++) {
                int col = nw * 32 + ni * 8 + l4 * 2 + l;
                float m = -INFINITY;
                #pragma unroll
                for (int mi = 0; mi < 4; mi++) {
                    m = fmaxf(m, acc[mi][ni][l]     + bo[mi][0]);
                    m = fmaxf(m, acc[mi][ni][2 + l] + bo[mi][1]);
                }
                atomicMaxFloat(&red[gq * 128 + col], m);
            }
        }
        __syncthreads();
        for (int t = tid; t < 1024; t += 256) {
            int cls = t >> 7, col = t & 127;
            unsigned idx = ((unsigned)cls * 9216u + (unsigned)(p0 + col)) % 24576u;
            atomicMaxFloat(&g_FQM[idx], red[t]);
        }
    }
}

// ---------------------------------------------------------------------------
// out[e] *= (1 + g_FQM[e % 24576]), float4.
__global__ __launch_bounds__(256) void mask_epilogue(float* __restrict__ out) {
    unsigned v = blockIdx.x * 256u + threadIdx.x;
    unsigned idx = (v * 4u) % 24576u;
    float4 o = ((float4*)out)[v];
    float4 m = *(const float4*)&g_FQM[idx];
    o.x *= (1.0f + m.x);
    o.y *= (1.0f + m.y);
    o.z *= (1.0f + m.z);
    o.w *= (1.0f + m.w);
    ((float4*)out)[v] = o;
}

// ---------------------------------------------------------------------------
extern "C" void kernel_launch(void* const* d_in, const int* in_sizes, int n_in,
                              void* d_out, int out_size) {
    const float* fuse = (const float*)d_in[0];
    const float* Wq   = (const float*)d_in[1];
    const float* bq   = (const float*)d_in[2];
    // d_in[3] (Wk), d_in[4] (bk): dead code — softmax over batch axis of size 1
    const float* Wv   = (const float*)d_in[5];
    const float* bv   = (const float*)d_in[6];
    float* out = (float*)d_out;

    // Not a stream op; safe on every call (incl. under graph capture).
    cudaFuncSetAttribute(gemm_mma<0>,
        cudaFuncAttributeMaxDynamicSharedMemorySize, SMEM_U32 * 4);
    cudaFuncSetAttribute(gemm_mma<1>,
        cudaFuncAttributeMaxDynamicSharedMemorySize, SMEM_U32 * 4);

    convert_kernel<<<(NPIX/4 + 32768 + 255) / 256, 256>>>(fuse, Wq, Wv);
    freq_kernel<<<C_DIM, 256>>>(fuse);   // also initializes g_FQM
    gemm_mma<0><<<dim3(72, 2), 256, SMEM_U32 * 4>>>(bq, nullptr);
    gemm_mma<1><<<dim3(72, 2), 256, SMEM_U32 * 4>>>(bv, out);
    mask_epilogue<<<NPIX / 4 / 256, 256>>>(out);
}

// round 13
// speedup vs baseline: 1.5123x; 1.1887x over previous
#include <cuda_runtime.h>
#include <cuda_bf16.h>
#include <math.h>
#include <stdint.h>

// Problem constants: B=1, C=256, H=W=96
#define C_DIM 256
#define HDIM  96
#define HW    9216          // H*W
#define CW    24576         // C*W
#define NPIX  (C_DIM*HW)    // 2359296

// ---------------------------------------------------------------------------
// Device-global scratch. bf16 split hi/lo, packed bf16x2 (uint32).
// X / FQ stored TRANSPOSED: [p][c/2] so GEMM B-fragments stage as uint4 copies.
__device__ float    g_FQ[NPIX];                     // fp32 FQ [ch][p]
__device__ uint32_t g_Xth[NPIX/2],  g_Xtl[NPIX/2];  // fuse^T hi/lo [p][c/2]
__device__ uint32_t g_FQth[NPIX/2], g_FQtl[NPIX/2]; // FQ^T   hi/lo [p][c/2]
__device__ uint32_t g_Wh0[32768], g_Wl0[32768];     // Wq hi/lo [o][c/2]
__device__ uint32_t g_Wh1[32768], g_Wl1[32768];     // Wv hi/lo [o][c/2]
__device__ float    g_FQM[CW];                      // Fuse_Q_mask

// ---------------------------------------------------------------------------
__device__ __forceinline__ void atomicMaxFloat(float* addr, float val) {
    if (val >= 0.0f) atomicMax((int*)addr, __float_as_int(val));
    else             atomicMin((unsigned int*)addr, __float_as_uint(val));
}

__device__ __forceinline__ uint32_t pack_bf2(float a, float b) {
    __nv_bfloat16 ha = __float2bfloat16_rn(a);
    __nv_bfloat16 hb = __float2bfloat16_rn(b);
    unsigned short ua = *reinterpret_cast<unsigned short*>(&ha);
    unsigned short ub = *reinterpret_cast<unsigned short*>(&hb);
    return (uint32_t)ua | ((uint32_t)ub << 16);
}
__device__ __forceinline__ float bf_hi_val(float a) {
    __nv_bfloat16 h = __float2bfloat16_rn(a);
    return __bfloat162float(h);
}

// m16n8k16 bf16 MMA, fp32 accumulate (standard PTX, compiles on plain sm_103)
__device__ __forceinline__ void mma16816(float* d, const uint32_t* a,
                                         const uint32_t* b) {
    asm volatile(
        "mma.sync.aligned.m16n8k16.row.col.f32.bf16.bf16.f32 "
        "{%0,%1,%2,%3}, {%4,%5,%6,%7}, {%8,%9}, {%0,%1,%2,%3};"
        : "+f"(d[0]), "+f"(d[1]), "+f"(d[2]), "+f"(d[3])
        : "r"(a[0]), "r"(a[1]), "r"(a[2]), "r"(a[3]), "r"(b[0]), "r"(b[1]));
}

// ---------------------------------------------------------------------------
// Convert Wq, Wv to split bf16 hi/lo (row-major [o][c/2], no transpose).
__global__ __launch_bounds__(256) void convert_w(
    const float* __restrict__ Wq, const float* __restrict__ Wv)
{
    unsigned v = blockIdx.x * 256u + threadIdx.x;   // float4 index
    const float* src; uint32_t *dh, *dl; unsigned base;
    if (v < 16384)      { src = Wq; dh = g_Wh0; dl = g_Wl0; base = v; }
    else if (v < 32768) { src = Wv; dh = g_Wh1; dl = g_Wl1; base = v - 16384; }
    else return;
    float4 x = ((const float4*)src)[base];
    float h0 = bf_hi_val(x.x), h1 = bf_hi_val(x.y);
    float h2 = bf_hi_val(x.z), h3 = bf_hi_val(x.w);
    dh[2*base]   = pack_bf2(x.x, x.y);
    dh[2*base+1] = pack_bf2(x.z, x.w);
    dl[2*base]   = pack_bf2(x.x - h0, x.y - h1);
    dl[2*base+1] = pack_bf2(x.z - h2, x.w - h3);
}

// ---------------------------------------------------------------------------
// Transpose + split-convert: src fp32 [256][9216] -> dh/dl u32 [9216][128],
// each u32 = (bf16(src[2cw][p]), bf16(src[2cw+1][p])). Tile 32c x 64p.
// SRC=0: src = xin (fuse, harness ptr), dest = g_Xth/g_Xtl.
// SRC=1: src = g_FQ (device global, bound IN DEVICE CODE), dest = g_FQth/tl.
template <int SRC>
__global__ __launch_bounds__(256) void transpose_convert(
    const float* __restrict__ xin)
{
    const float* src = (SRC == 0) ? xin : (const float*)g_FQ;
    uint32_t* dh = (SRC == 0) ? g_Xth : g_FQth;
    uint32_t* dl = (SRC == 0) ? g_Xtl : g_FQtl;

    __shared__ float ts[32][65];
    const int p0 = blockIdx.x * 64;
    const int c0 = blockIdx.y * 32;
    const int tid = threadIdx.x;
    #pragma unroll
    for (int k = 0; k < 8; k++) {
        int idx = k * 256 + tid;
        int c = idx >> 6, p = idx & 63;
        ts[c][p] = src[(size_t)(c0 + c) * HW + p0 + p];
    }
    __syncthreads();
    #pragma unroll
    for (int k = 0; k < 4; k++) {
        int idx = k * 256 + tid;
        int p = idx >> 4, cw = idx & 15;
        float a = ts[2*cw][p], b = ts[2*cw + 1][p];
        float ah = bf_hi_val(a), bh = bf_hi_val(b);
        size_t o = (size_t)(p0 + p) * 128 + (c0 >> 1) + cw;
        dh[o] = pack_bf2(a, b);
        dl[o] = pack_bf2(a - ah, b - bh);
    }
}

// ---------------------------------------------------------------------------
// Per-channel frequency filter (proven R6 kernel), fp32 output g_FQ.
// Keep DFT freqs kr,kc in {-2..1}, inverse-synthesize, abs, /9216.
__global__ __launch_bounds__(256) void freq_kernel(const float* __restrict__ x) {
    __shared__ float sa[HW];
    __shared__ float twc[96], tws[96];
    __shared__ unsigned char pidx[4][96];
    __shared__ float Gp[2][4][96][2];
    __shared__ float s2p[64][2];
    __shared__ float sF[32];
    __shared__ float sP[4][96][2];
    __shared__ float sMin[8], sMax[8];

    const int ch  = blockIdx.x;
    const int tid = threadIdx.x;
    const float* xc = x + ch * HW;

    if (ch < 96) g_FQM[ch * 256 + tid] = -INFINITY;   // init Fuse_Q_mask buffer

    if (tid < 96) {  // twiddles, fp64 trig
        double th = 2.0 * 3.14159265358979323846 * (double)tid / 96.0;
        twc[tid] = (float)cos(th);
        tws[tid] = (float)sin(th);
    }
    for (int t = tid; t < 384; t += 256) {
        int k = t / 96, v = t - k * 96;
        int m = ((k - 2) * v) % 96; if (m < 0) m += 96;
        pidx[k][v] = (unsigned char)m;
    }

    float lmin = INFINITY, lmax = -INFINITY;
    for (int i = tid; i < HW; i += 256) {
        float a = fabsf(xc[i]);
        sa[i] = a;
        lmin = fminf(lmin, a);
        lmax = fmaxf(lmax, a);
    }
    #pragma unroll
    for (int off = 16; off; off >>= 1) {
        lmin = fminf(lmin, __shfl_down_sync(0xffffffffu, lmin, off));
        lmax = fmaxf(lmax, __shfl_down_sync(0xffffffffu, lmax, off));
    }
    const int wid = tid >> 5, lane = tid & 31;
    if (lane == 0) { sMin[wid] = lmin; sMax[wid] = lmax; }
    __syncthreads();

    float mn = sMin[0], mx = sMax[0];
    #pragma unroll
    for (int j = 1; j < 8; j++) { mn = fminf(mn, sMin[j]); mx = fmaxf(mx, sMax[j]); }
    const float ptp = mx - mn;

    // stage 1: column DFT over h
    if (tid < 192) {
        const int w  = tid >> 1;
        const int h0 = (tid & 1) * 48;
        float gr[4] = {0.f, 0.f, 0.f, 0.f};
        float gi[4] = {0.f, 0.f, 0.f, 0.f};
        for (int j = 0; j < 48; j++) {
            int h = h0 + j;
            float q = floorf(__fdiv_rn(255.0f * (sa[h * 96 + w] - mn), ptp));
            #pragma unroll
            for (int kr = 0; kr < 4; kr++) {
                int m = pidx[kr][h];
                gr[kr] += q * twc[m];
                gi[kr] -= q * tws[m];
            }
        }
        #pragma unroll
        for (int kr = 0; kr < 4; kr++) {
            Gp[tid & 1][kr][w][0] = gr[kr];
            Gp[tid & 1][kr][w][1] = gi[kr];
        }
    }
    __syncthreads();

    // stage 2: 16 coefficients
    if (tid < 64) {
        int coef = tid >> 2, q4 = tid & 3;
        int kr = coef >> 2, kc = coef & 3;
        float fr = 0.f, fi = 0.f;
        int w0 = q4 * 24;
        for (int w = w0; w < w0 + 24; w++) {
            float grw = Gp[0][kr][w][0] + Gp[1][kr][w][0];
            float giw = Gp[0][kr][w][1] + Gp[1][kr][w][1];
            int m = pidx[kc][w];
            float cc = twc[m], ss = tws[m];
            fr += grw * cc + giw * ss;
            fi += giw * cc - grw * ss;
        }
        s2p[tid][0] = fr;
        s2p[tid][1] = fi;
    }
    __syncthreads();
    if (tid < 32) {
        int coef = tid >> 1, ri = tid & 1;
        sF[coef * 2 + ri] = s2p[coef * 4][ri] + s2p[coef * 4 + 1][ri]
                          + s2p[coef * 4 + 2][ri] + s2p[coef * 4 + 3][ri];
    }
    __syncthreads();

    // synthesis column partials
    if (tid < 96) {
        int w = tid;
        #pragma unroll
        for (int kr = 0; kr < 4; kr++) {
            float pre = 0.f, pim = 0.f;
            #pragma unroll
            for (int kc = 0; kc < 4; kc++) {
                int m = pidx[kc][w];
                float fr = sF[2 * (kr * 4 + kc)], fi = sF[2 * (kr * 4 + kc) + 1];
                float cc = twc[m], ss = tws[m];
                pre += fr * cc - fi * ss;
                pim += fr * ss + fi * cc;
            }
            sP[kr][w][0] = pre;
            sP[kr][w][1] = pim;
        }
    }
    __syncthreads();

    const float inv = 1.0f / 9216.0f;
    for (int i = tid; i < HW; i += 256) {
        int h = i / 96, w = i - h * 96;
        float re = 0.f, im = 0.f;
        #pragma unroll
        for (int kr = 0; kr < 4; kr++) {
            int m = pidx[kr][h];
            float cc = twc[m], ss = tws[m];
            float pre = sP[kr][w][0], pim = sP[kr][w][1];
            re += pre * cc - pim * ss;
            im += pre * ss + pim * cc;
        }
        g_FQ[ch * HW + i] = sqrtf(re * re + im * im) * inv;
    }
}

// ---------------------------------------------------------------------------
// Split-precision bf16 GEMM via mma.sync.m16n8k16 (HMMA tensor pipe).
// out[o,p] = sum_c W[o,c] X[c,p] + bias[o],  O=256, P=9216, K=256.
// CTA tile: M=128 x N=64, K staged in 4 phases of 64. 55 KB smem -> 2 CTA/SM.
// 8 warps as 2m x 4n (warp tile 64x16). 3 passes: Ah*Bh + Ah*Bl + Al*Bh.
// Both operands pre-packed as k-pair bf16x2 -> staging is pure uint4 copies.
// MODE 0 (Q): X = FQ^T, epilogue class-max into g_FQM.
// MODE 1 (V): X = fuse^T, writes raw (acc+bias) to out.
#define APITCH 36            // u32 per smem row (72 bf16; 36%32=4 -> no conflicts)
#define AH_OFF 0
#define AL_OFF 4608          // 128*36
#define BH_OFF 9216
#define BL_OFF 11520         // +64*36
#define SMEM_U32 13824       // 55296 bytes

template <int MODE>
__global__ __launch_bounds__(256, 2) void gemm_mma(
    const float* __restrict__ bias, float* __restrict__ out)
{
    extern __shared__ uint32_t su[];
    const int tid  = threadIdx.x;
    const int wid  = tid >> 5, lane = tid & 31;
    const int mw   = wid >> 2, nw = wid & 3;     // 2m x 4n warp grid
    const int gq   = lane >> 2, l4 = lane & 3;   // groupID, threadID-in-group
    const int p0   = blockIdx.x * 64;
    const int o0   = blockIdx.y * 128;

    const uint32_t* Ah = (MODE == 0) ? g_Wh0  : g_Wh1;
    const uint32_t* Al = (MODE == 0) ? g_Wl0  : g_Wl1;
    const uint32_t* Xh = (MODE == 0) ? g_FQth : g_Xth;
    const uint32_t* Xl = (MODE == 0) ? g_FQtl : g_Xtl;

    float acc[4][2][4];
    #pragma unroll
    for (int mi = 0; mi < 4; mi++)
        #pragma unroll
        for (int ni = 0; ni < 2; ni++)
            #pragma unroll
            for (int r = 0; r < 4; r++) acc[mi][ni][r] = 0.f;

    #pragma unroll 1
    for (int kb = 0; kb < 4; kb++) {
        // ---- stage A: 128 o-rows x 8 uint4 (64 c), hi+lo ------------------
        #pragma unroll
        for (int f = tid; f < 1024; f += 256) {
            int o = f >> 3, q = f & 7;
            uint4 vh = ((const uint4*)Ah)[(o0 + o) * 32 + kb * 8 + q];
            uint4 vl = ((const uint4*)Al)[(o0 + o) * 32 + kb * 8 + q];
            ((uint4*)(su + AH_OFF + o * APITCH))[q] = vh;
            ((uint4*)(su + AL_OFF + o * APITCH))[q] = vl;
        }
        // ---- stage B: 64 p-rows x 8 uint4 (64 c), hi+lo -------------------
        #pragma unroll
        for (int f = tid; f < 512; f += 256) {
            int p = f >> 3, q = f & 7;
            uint4 vh = ((const uint4*)Xh)[(size_t)(p0 + p) * 32 + kb * 8 + q];
            uint4 vl = ((const uint4*)Xl)[(size_t)(p0 + p) * 32 + kb * 8 + q];
            ((uint4*)(su + BH_OFF + p * APITCH))[q] = vh;
            ((uint4*)(su + BL_OFF + p * APITCH))[q] = vl;
        }
        __syncthreads();

        // ---- compute: 4 k-steps of 16 -------------------------------------
        #pragma unroll 1
        for (int ks = 0; ks < 4; ks++) {
            const int k0w = ks * 8;
            uint32_t bh[2][2], bl[2][2];
            #pragma unroll
            for (int ni = 0; ni < 2; ni++) {
                int n = nw * 16 + ni * 8 + gq;
                int base = BH_OFF + n * APITCH + k0w + l4;
                bh[ni][0] = su[base];
                bh[ni][1] = su[base + 4];
                bl[ni][0] = su[base + (BL_OFF - BH_OFF)];
                bl[ni][1] = su[base + (BL_OFF - BH_OFF) + 4];
            }
            #pragma unroll
            for (int mi = 0; mi < 4; mi++) {
                int row = mw * 64 + mi * 16 + gq;
                int base = AH_OFF + row * APITCH + k0w + l4;
                uint32_t ah[4], al[4];
                ah[0] = su[base];
                ah[1] = su[base + 8 * APITCH];
                ah[2] = su[base + 4];
                ah[3] = su[base + 8 * APITCH + 4];
                al[0] = su[base + AL_OFF];
                al[1] = su[base + AL_OFF + 8 * APITCH];
                al[2] = su[base + AL_OFF + 4];
                al[3] = su[base + AL_OFF + 8 * APITCH + 4];
                #pragma unroll
                for (int ni = 0; ni < 2; ni++) {
                    mma16816(acc[mi][ni], ah, bh[ni]);
                    mma16816(acc[mi][ni], ah, bl[ni]);
                    mma16816(acc[mi][ni], al, bh[ni]);
                }
            }
        }
        __syncthreads();
    }

    // ---- epilogue --------------------------------------------------------
    if (MODE == 1) {
        #pragma unroll
        for (int mi = 0; mi < 4; mi++) {
            int o = o0 + mw * 64 + mi * 16 + gq;
            float b0 = bias[o], b1 = bias[o + 8];
            #pragma unroll
            for (int ni = 0; ni < 2; ni++) {
                int p = p0 + nw * 16 + ni * 8 + l4 * 2;
                float2 v0 = { acc[mi][ni][0] + b0, acc[mi][ni][1] + b0 };
                float2 v1 = { acc[mi][ni][2] + b1, acc[mi][ni][3] + b1 };
                *(float2*)(out + (size_t)o * HW + p)       = v0;
                *(float2*)(out + (size_t)(o + 8) * HW + p) = v1;
            }
        }
    } else {
        // row class (o mod 8) == gq for every acc this thread holds
        float* red = (float*)su;                 // 8 x 64
        for (int t = tid; t < 512; t += 256) red[t] = -INFINITY;
        __syncthreads();
        float bo[4][2];
        #pragma unroll
        for (int mi = 0; mi < 4; mi++) {
            int o = o0 + mw * 64 + mi * 16 + gq;
            bo[mi][0] = bias[o];
            bo[mi][1] = bias[o + 8];
        }
        #pragma unroll
        for (int ni = 0; ni < 2; ni++) {
            #pragma unroll
            for (int l = 0; l < 2; l++) {
                int col = nw * 16 + ni * 8 + l4 * 2 + l;
                float m = -INFINITY;
                #pragma unroll
                for (int mi = 0; mi < 4; mi++) {
                    m = fmaxf(m, acc[mi][ni][l]     + bo[mi][0]);
                    m = fmaxf(m, acc[mi][ni][2 + l] + bo[mi][1]);
                }
                atomicMaxFloat(&red[gq * 64 + col], m);
            }
        }
        __syncthreads();
        for (int t = tid; t < 512; t += 256) {
            int cls = t >> 6, col = t & 63;
            unsigned idx = ((unsigned)cls * 9216u + (unsigned)(p0 + col)) % 24576u;
            atomicMaxFloat(&g_FQM[idx], red[t]);
        }
    }
}

// ---------------------------------------------------------------------------
// out[e] *= (1 + g_FQM[e % 24576]), float4.
__global__ __launch_bounds__(256) void mask_epilogue(float* __restrict__ out) {
    unsigned v = blockIdx.x * 256u + threadIdx.x;
    unsigned idx = (v * 4u) % 24576u;
    float4 o = ((float4*)out)[v];
    float4 m = *(const float4*)&g_FQM[idx];
    o.x *= (1.0f + m.x);
    o.y *= (1.0f + m.y);
    o.z *= (1.0f + m.z);
    o.w *= (1.0f + m.w);
    ((float4*)out)[v] = o;
}

// ---------------------------------------------------------------------------
extern "C" void kernel_launch(void* const* d_in, const int* in_sizes, int n_in,
                              void* d_out, int out_size) {
    const float* fuse = (const float*)d_in[0];
    const float* Wq   = (const float*)d_in[1];
    const float* bq   = (const float*)d_in[2];
    // d_in[3] (Wk), d_in[4] (bk): dead code — softmax over batch axis of size 1
    const float* Wv   = (const float*)d_in[5];
    const float* bv   = (const float*)d_in[6];
    float* out = (float*)d_out;

    cudaFuncSetAttribute(gemm_mma<0>,
        cudaFuncAttributeMaxDynamicSharedMemorySize, SMEM_U32 * 4);
    cudaFuncSetAttribute(gemm_mma<1>,
        cudaFuncAttributeMaxDynamicSharedMemorySize, SMEM_U32 * 4);

    static cudaStream_t s1 = nullptr;
    static cudaEvent_t evRoot = nullptr, evT = nullptr;
    if (s1 == nullptr) {
        cudaStreamCreateWithFlags(&s1, cudaStreamNonBlocking);
        cudaEventCreateWithFlags(&evRoot, cudaEventDisableTiming);
        cudaEventCreateWithFlags(&evT, cudaEventDisableTiming);
    }

    // Side stream: freq path (independent of W/X conversion).
    cudaEventRecord(evRoot, 0);
    cudaStreamWaitEvent(s1, evRoot, 0);
    freq_kernel<<<C_DIM, 256, 0, s1>>>(fuse);          // also inits g_FQM
    transpose_convert<1><<<dim3(144, 8), 256, 0, s1>>>(nullptr);   // FQ -> FQ^T
    cudaEventRecord(evT, s1);

    // Main stream: convert -> V-GEMM (overlaps freq), then Q-GEMM, mask.
    convert_w<<<128, 256>>>(Wq, Wv);
    transpose_convert<0><<<dim3(144, 8), 256>>>(fuse);             // fuse -> X^T
    gemm_mma<1><<<dim3(144, 2), 256, SMEM_U32 * 4>>>(bv, out);
    cudaStreamWaitEvent(0, evT, 0);
    gemm_mma<0><<<dim3(144, 2), 256, SMEM_U32 * 4>>>(bq, nullptr);
    mask_epilogue<<<NPIX / 4 / 256, 256>>>(out);
}